// round 15
// baseline (speedup 1.0000x reference)
#include <cuda_runtime.h>
#include <math.h>

// Problem constants
#define NV    5000
#define NFC   10000
#define LAYERS 30
#define NNZT  480000
#define EPSBN 1e-5f

typedef unsigned long long u64t;

// ---------------- device scratch ----------------
__device__ __align__(16) float g_v [NV  * 128];
__device__ __align__(16) float g_ev[NV  * 128];
__device__ __align__(16) float g_ef[NFC * 128];
__device__ __align__(16) float g_ex[NV  * 128];
__device__ __align__(16) float g_Dv[NFC * 128];
__device__ __align__(16) float g_DA[NV  * 128];
__device__ float g_stats[64 * 512];
__device__ float g_a   [128];
__device__ float g_bout[1];
__device__ int   g_sync[256];   // 4 ints per fused phase-pair, zeroed at graph start

__device__ __forceinline__ float eluf(float x) {
    return x > 0.f ? x : (__expf(x) - 1.f);
}

// packed f32x2 FMA: two independent IEEE fp32 FMAs
__device__ __forceinline__ void ffma2(u64t& d, u64t a, u64t b) {
    asm("fma.rn.f32x2 %0, %1, %2, %0;" : "+l"(d) : "l"(a), "l"(b));
}
__device__ __forceinline__ u64t bcast2(float x) {
    u64t r; asm("mov.b64 %0, {%1, %1};" : "=l"(r) : "f"(x)); return r;
}

__device__ __forceinline__ void spin_done(int* p, int W) {
    for (;;) {
        int v;
        asm volatile("ld.acquire.gpu.b32 %0, [%1];" : "=r"(v) : "l"(p));
        if (v >= W) break;
        __nanosleep(64);
    }
}

// ---------------- input projection ----------------
__global__ void k_in(const float* __restrict__ in, const float* __restrict__ Wi,
                     const float* __restrict__ bi, float* __restrict__ statp) {
    int c = threadIdx.x;  // 128
    float w0 = Wi[c], w1 = Wi[128 + c], w2 = Wi[256 + c], b = bi[c];
    float s = 0.f, s2 = 0.f;
    for (int n = blockIdx.x; n < NV; n += gridDim.x) {
        float val = b + in[n * 3] * w0 + in[n * 3 + 1] * w1 + in[n * 3 + 2] * w2;
        g_v [n * 128 + c] = val;
        float e = eluf(val);
        g_ev[n * 128 + c] = e;
        s += e; s2 += e * e;
    }
    atomicAdd(&statp[c], s);
    atomicAdd(&statp[256 + c], s2);
}

// ---------------- column stats kernel (head only) ----------------
__global__ void __launch_bounds__(256)
k_stats128(const float4* __restrict__ X4, int rows,
           float* __restrict__ statp, int off) {
    __shared__ float r1[8][128];
    __shared__ float r2[8][128];
    int tid = threadIdx.x;
    int c4 = tid & 31;
    int g  = tid >> 5;
    float4 s  = make_float4(0.f, 0.f, 0.f, 0.f);
    float4 s2 = make_float4(0.f, 0.f, 0.f, 0.f);
    for (int r = blockIdx.x * 8 + g; r < rows; r += gridDim.x * 8) {
        float4 x = X4[r * 32 + c4];
        s.x += x.x; s.y += x.y; s.z += x.z; s.w += x.w;
        s2.x += x.x * x.x; s2.y += x.y * x.y;
        s2.z += x.z * x.z; s2.w += x.w * x.w;
    }
    r1[g][c4 * 4 + 0] = s.x;  r1[g][c4 * 4 + 1] = s.y;
    r1[g][c4 * 4 + 2] = s.z;  r1[g][c4 * 4 + 3] = s.w;
    r2[g][c4 * 4 + 0] = s2.x; r2[g][c4 * 4 + 1] = s2.y;
    r2[g][c4 * 4 + 2] = s2.z; r2[g][c4 * 4 + 3] = s2.w;
    __syncthreads();
    if (tid < 128) {
        float a = 0.f;
#pragma unroll
        for (int w = 0; w < 8; w++) a += r1[w][tid];
        atomicAdd(&statp[off + tid], a);
    } else {
        int c = tid - 128;
        float a = 0.f;
#pragma unroll
        for (int w = 0; w < 8; w++) a += r2[w][c];
        atomicAdd(&statp[256 + off + c], a);
    }
}

// ---------------- GEMM core (R14, FFMA2 inner loop) ----------------
// out = (A*a) @ W + bias [+ V];  A = [L | R] split, each [rows,128]; 64x64 CTA tile.
template<int KT, bool ACC>
__device__ __forceinline__ void gemm_core(
    const float* __restrict__ L, const float* __restrict__ R, int rows,
    const float* __restrict__ W, const float* __restrict__ bvec,
    const float* __restrict__ gamma, const float* __restrict__ beta,
    const float* __restrict__ statp_in, float invn,
    float* __restrict__ Vout, float* __restrict__ Eout,
    float* __restrict__ statp_out) {
    __shared__ __align__(16) float As[2][16][72];
    __shared__ __align__(16) float Bs[2][16][72];
    __shared__ float sSc[256];
    __shared__ float sT [256];
    __shared__ float sB [64];
    __shared__ float sBp[256];
    int tid = threadIdx.x;  // 256
    int col0 = blockIdx.y * 64;

    if (KT == 16 || tid < 128) {
        float mean = statp_in[tid] * invn;
        float var  = fmaxf(statp_in[256 + tid] * invn - mean * mean, 0.f);
        float a = gamma[tid] * rsqrtf(var + EPSBN);
        sSc[tid] = a;
        sT[tid]  = beta[tid] - mean * a;
    } else {
        sT[tid] = beta[tid];   // broadcast-avg columns: var==0 -> BN out == beta
    }
    __syncthreads();

    int row0 = blockIdx.x * 64;
    int wc = tid & 31, wr = tid >> 5;
    u64t acc2[4][2];
#pragma unroll
    for (int p = 0; p < 4; p++) { acc2[p][0] = 0ull; acc2[p][1] = 0ull; }
    float biasAcc = 0.f;
    int bcol = tid & 63, bq = tid >> 6;

    int am = tid >> 2, ak4 = (tid & 3) * 4;
    int bk = tid >> 4, bc = (tid & 15) * 4;
    float4 rA, rB;

    auto loadRegs = [&](int t) {
        int k0 = t * 16;
        const float* Ab = (KT == 16 && k0 >= 128) ? R : L;
        int r = row0 + am;
        rA = make_float4(0.f, 0.f, 0.f, 0.f);
        if (r < rows) rA = *(const float4*)&Ab[r * 128 + (k0 & 127) + ak4];
        rB = *(const float4*)&W[(k0 + bk) * 128 + col0 + bc];
    };
    auto storeSmem = [&](int t, int b) {
        int k0 = t * 16;
        As[b][ak4 + 0][am] = rA.x * sSc[k0 + ak4 + 0];
        As[b][ak4 + 1][am] = rA.y * sSc[k0 + ak4 + 1];
        As[b][ak4 + 2][am] = rA.z * sSc[k0 + ak4 + 2];
        As[b][ak4 + 3][am] = rA.w * sSc[k0 + ak4 + 3];
        *(float4*)&Bs[b][bk][bc] = rB;
    };

    loadRegs(0);
    storeSmem(0, 0);
    __syncthreads();
#pragma unroll 1
    for (int t = 0; t < KT; t++) {
        int b = t & 1;
        if (t + 1 < KT) loadRegs(t + 1);
        {   // balanced bias fold: 4 FMAs per thread per tile
            int kq = bq * 4;
#pragma unroll
            for (int k = 0; k < 4; k++)
                biasAcc += sT[t * 16 + kq + k] * Bs[b][kq + k][bcol];
        }
#pragma unroll
        for (int k = 0; k < 16; k++) {
            const ulonglong2* ap = (const ulonglong2*)&As[b][k][wr * 8];
            ulonglong2 aA = ap[0];
            ulonglong2 aB = ap[1];
            float2 b2 = *(const float2*)&Bs[b][k][wc * 2];
            u64t bx = bcast2(b2.x), by = bcast2(b2.y);
            ffma2(acc2[0][0], aA.x, bx); ffma2(acc2[0][1], aA.x, by);
            ffma2(acc2[1][0], aA.y, bx); ffma2(acc2[1][1], aA.y, by);
            ffma2(acc2[2][0], aB.x, bx); ffma2(acc2[2][1], aB.x, by);
            ffma2(acc2[3][0], aB.y, bx); ffma2(acc2[3][1], aB.y, by);
        }
        if (t + 1 < KT) storeSmem(t + 1, b ^ 1);
        __syncthreads();
    }

    float acc[8][2];
#pragma unroll
    for (int p = 0; p < 4; p++)
#pragma unroll
        for (int c = 0; c < 2; c++)
            asm("mov.b64 {%0, %1}, %2;"
                : "=f"(acc[2 * p][c]), "=f"(acc[2 * p + 1][c]) : "l"(acc2[p][c]));

    if (KT == 8) {
        int r0 = 128 + bq * 32;
#pragma unroll 8
        for (int rr = 0; rr < 32; rr++)
            biasAcc += sT[r0 + rr] * W[(r0 + rr) * 128 + col0 + bcol];
    }
    sBp[bq * 64 + bcol] = biasAcc;
    __syncthreads();
    if (tid < 64)
        sB[tid] = sBp[tid] + sBp[64 + tid] + sBp[128 + tid] + sBp[192 + tid]
                + bvec[col0 + tid];
    __syncthreads();

    float s1v[2] = {0.f, 0.f};
    float s2v[2] = {0.f, 0.f};
#pragma unroll
    for (int i = 0; i < 8; i++) {
        int r = row0 + wr * 8 + i;
        if (r >= rows) continue;
        int C = col0 + wc * 2;
        float v0 = acc[i][0] + sB[wc * 2];
        float v1 = acc[i][1] + sB[wc * 2 + 1];
        if (ACC) {
            float2 old = *(float2*)&Vout[r * 128 + C];
            v0 += old.x; v1 += old.y;
            *(float2*)&Vout[r * 128 + C] = make_float2(v0, v1);
        }
        float e0 = eluf(v0), e1 = eluf(v1);
        *(float2*)&Eout[r * 128 + C] = make_float2(e0, e1);
        s1v[0] += e0; s1v[1] += e1;
        s2v[0] += e0 * e0; s2v[1] += e1 * e1;
    }
    float* red1 = &As[0][0][0];
    float* red2 = &As[1][0][0];
    red1[wr * 64 + wc * 2]     = s1v[0];
    red1[wr * 64 + wc * 2 + 1] = s1v[1];
    red2[wr * 64 + wc * 2]     = s2v[0];
    red2[wr * 64 + wc * 2 + 1] = s2v[1];
    __syncthreads();
    if (tid < 64) {
        float s = 0.f;
#pragma unroll
        for (int w = 0; w < 8; w++) s += red1[w * 64 + tid];
        atomicAdd(&statp_out[col0 + tid], s);
    } else if (tid < 128) {
        int c = tid - 64;
        float s = 0.f;
#pragma unroll
        for (int w = 0; w < 8; w++) s += red2[w * 64 + c];
        atomicAdd(&statp_out[256 + col0 + c], s);
    }
}

// ---------------- fused even-layer megakernel: spMM -> stats -> GEMM -------------
// Work-stealing phases with device-wide done counters (deadlock-free: chunks are
// ticket-stolen, so resident CTAs finish all work; latecomers see the done flag).
template<bool ACC>
__global__ void __launch_bounds__(256)
k_mega(const int* __restrict__ erows, const int* __restrict__ ecols,
       const float* __restrict__ evals, const float* __restrict__ Xsp,
       float* __restrict__ Ybuf, int yrows, int* __restrict__ sync,
       const float* __restrict__ L, const float* __restrict__ R, int rows,
       const float* __restrict__ W, const float* __restrict__ bvec,
       const float* __restrict__ gamma, const float* __restrict__ beta,
       float* __restrict__ statp_in, float invn,
       float* __restrict__ Vout, float* __restrict__ Eout,
       float* __restrict__ statp_out) {
    int tid = threadIdx.x;
    __shared__ int sCh;

    // ---- phase 1: COO spMM (vector atomics), chunks of 1024 edges ----
    {
        const int nch = (NNZT + 1023) >> 10;
        int done_local = 0;
        for (;;) {
            if (tid == 0) sCh = atomicAdd(&sync[0], 1);
            __syncthreads();
            int ch = sCh;
            __syncthreads();
            if (ch >= nch) break;
            int base = ch << 10;
#pragma unroll 4
            for (int l = tid; l < 8192; l += 256) {
                int e = base + (l >> 3);
                if (e < NNZT) {
                    int d = l & 7;
                    int Rr = erows[e], Cq = ecols[e];
                    float v = evals[e];
                    float4 xv = ((const float4*)Xsp)[(Cq >> 2) * 32 + (Cq & 3) * 8 + d];
                    float4* yp = (float4*)Ybuf + (Rr >> 2) * 32 + (Rr & 3) * 8 + d;
                    asm volatile("red.global.add.v4.f32 [%0], {%1,%2,%3,%4};"
                                 :: "l"(yp), "f"(v * xv.x), "f"(v * xv.y),
                                    "f"(v * xv.z), "f"(v * xv.w) : "memory");
                }
            }
            done_local++;
        }
        __threadfence();
        __syncthreads();
        if (tid == 0 && done_local) atomicAdd(&sync[1], done_local);
        if (tid == 0) spin_done(&sync[1], nch);
        __syncthreads();
    }

    // ---- phase 2: column stats of Ybuf -> statp_in[128..], chunks of 256 rows ----
    {
        __shared__ float r1[8][128];
        __shared__ float r2[8][128];
        const int nch = (yrows + 255) >> 8;
        int c4 = tid & 31, g = tid >> 5;
        float4 s  = make_float4(0.f, 0.f, 0.f, 0.f);
        float4 s2 = make_float4(0.f, 0.f, 0.f, 0.f);
        int done_local = 0;
        for (;;) {
            if (tid == 0) sCh = atomicAdd(&sync[2], 1);
            __syncthreads();
            int ch = sCh;
            __syncthreads();
            if (ch >= nch) break;
            int r0 = (ch << 8) + g;
#pragma unroll 4
            for (int it = 0; it < 32; it++) {
                int r = r0 + it * 8;
                if (r < yrows) {
                    float4 x = ((const float4*)Ybuf)[r * 32 + c4];
                    s.x += x.x; s.y += x.y; s.z += x.z; s.w += x.w;
                    s2.x += x.x * x.x; s2.y += x.y * x.y;
                    s2.z += x.z * x.z; s2.w += x.w * x.w;
                }
            }
            done_local++;
        }
        r1[g][c4 * 4 + 0] = s.x;  r1[g][c4 * 4 + 1] = s.y;
        r1[g][c4 * 4 + 2] = s.z;  r1[g][c4 * 4 + 3] = s.w;
        r2[g][c4 * 4 + 0] = s2.x; r2[g][c4 * 4 + 1] = s2.y;
        r2[g][c4 * 4 + 2] = s2.z; r2[g][c4 * 4 + 3] = s2.w;
        __syncthreads();
        if (tid < 128) {
            float a = 0.f;
#pragma unroll
            for (int w = 0; w < 8; w++) a += r1[w][tid];
            atomicAdd(&statp_in[128 + tid], a);
        } else {
            int c = tid - 128;
            float a = 0.f;
#pragma unroll
            for (int w = 0; w < 8; w++) a += r2[w][c];
            atomicAdd(&statp_in[256 + 128 + c], a);
        }
        __threadfence();
        __syncthreads();
        if (tid == 0 && done_local) atomicAdd(&sync[3], done_local);
        if (tid == 0) spin_done(&sync[3], nch);
        __syncthreads();
    }

    // ---- phase 3: fused BN + bias-fold + GEMM + elu + stats ----
    gemm_core<16, ACC>(L, R, rows, W, bvec, gamma, beta, statp_in, invn,
                       Vout, Eout, statp_out);
}

// ---------------- odd-layer GEMM (KT=8) + Dv/DA re-zero tail ----------------
template<bool ACC>
__global__ void __launch_bounds__(256)
k_gemm8(const float* __restrict__ L, int rows,
        const float* __restrict__ W, const float* __restrict__ bvec,
        const float* __restrict__ gamma, const float* __restrict__ beta,
        const float* __restrict__ statp_in, float invn,
        float* __restrict__ Vout, float* __restrict__ Eout,
        float* __restrict__ statp_out,
        float* __restrict__ Zbuf, int nz4) {
    gemm_core<8, ACC>(L, nullptr, rows, W, bvec, gamma, beta, statp_in, invn,
                      Vout, Eout, statp_out);
    // tail: zero Dv/DA for the next even layer (no concurrent readers)
    int gt = (blockIdx.y * gridDim.x + blockIdx.x) * 256 + threadIdx.x;
    int gs = gridDim.x * gridDim.y * 256;
    float4 z = make_float4(0.f, 0.f, 0.f, 0.f);
    for (int i = gt; i < nz4; i += gs) ((float4*)Zbuf)[i] = z;
}

// ---------------- final head ----------------
__global__ void k_head_prep(const float* __restrict__ gamma, const float* __restrict__ beta,
                            const float* __restrict__ Wout, const float* __restrict__ bout,
                            const float* __restrict__ statp, float invn) {
    __shared__ float sh[128];
    int c = threadIdx.x;  // 128
    float mean = statp[c] * invn;
    float var  = fmaxf(statp[256 + c] * invn - mean * mean, 0.f);
    float a = gamma[c] * rsqrtf(var + EPSBN);
    g_a[c] = a;
    sh[c] = (beta[c] - mean * a) * Wout[c];
    __syncthreads();
    for (int s = 64; s > 0; s >>= 1) {
        if (c < s) sh[c] += sh[c + s];
        __syncthreads();
    }
    if (c == 0) g_bout[0] = bout[0] + sh[0];
}

__global__ void k_final(const float* __restrict__ Wout, float* __restrict__ out) {
    int warp = (blockIdx.x * blockDim.x + threadIdx.x) >> 5;
    int lane = threadIdx.x & 31;
    if (warp >= NV) return;
    float s = 0.f;
#pragma unroll
    for (int q = 0; q < 4; q++) {
        int c = q * 32 + lane;
        s += g_v[warp * 128 + c] * g_a[c] * Wout[c];
    }
#pragma unroll
    for (int o = 16; o; o >>= 1) s += __shfl_xor_sync(0xffffffffu, s, o);
    if (lane == 0) out[warp] = eluf(s + g_bout[0]);
}

// ---------------- host orchestration ----------------
extern "C" void kernel_launch(void* const* d_in, const int* in_sizes, int n_in,
                              void* d_out, int out_size) {
    const float* inputs   = (const float*)d_in[0];
    const int*   Di_rows  = (const int*)d_in[2];
    const int*   Di_cols  = (const int*)d_in[3];
    const float* Di_vals  = (const float*)d_in[4];
    const int*   DiA_rows = (const int*)d_in[5];
    const int*   DiA_cols = (const int*)d_in[6];
    const float* DiA_vals = (const float*)d_in[7];
    const float* W_in  = (const float*)d_in[8];
    const float* b_in  = (const float*)d_in[9];
    const float* g0    = (const float*)d_in[10];
    const float* be0   = (const float*)d_in[11];
    const float* W0    = (const float*)d_in[12];
    const float* b0    = (const float*)d_in[13];
    const float* g1    = (const float*)d_in[14];
    const float* be1   = (const float*)d_in[15];
    const float* Wl1   = (const float*)d_in[16];
    const float* bl1   = (const float*)d_in[17];
    const float* g2    = (const float*)d_in[18];
    const float* be2   = (const float*)d_in[19];
    const float* W_out = (const float*)d_in[20];
    const float* b_out = (const float*)d_in[21];
    float* out = (float*)d_out;
    (void)in_sizes; (void)n_in; (void)out_size;

    float *p_v, *p_ev, *p_ef, *p_ex, *p_Dv, *p_DA, *p_stats;
    int* p_sync;
    cudaGetSymbolAddress((void**)&p_v,     g_v);
    cudaGetSymbolAddress((void**)&p_ev,    g_ev);
    cudaGetSymbolAddress((void**)&p_ef,    g_ef);
    cudaGetSymbolAddress((void**)&p_ex,    g_ex);
    cudaGetSymbolAddress((void**)&p_Dv,    g_Dv);
    cudaGetSymbolAddress((void**)&p_DA,    g_DA);
    cudaGetSymbolAddress((void**)&p_stats, g_stats);
    cudaGetSymbolAddress((void**)&p_sync,  g_sync);
    auto SB = [&](int i) { return p_stats + (size_t)i * 512; };

    const dim3 GF((NFC + 63) / 64, 2);
    const dim3 GN((NV  + 63) / 64, 2);
    const float INV_F = 1.0f / (float)NFC;
    const float INV_N = 1.0f / (float)NV;

    // replay-invariant init
    cudaMemsetAsync(p_stats, 0, (size_t)64 * 512 * sizeof(float));
    cudaMemsetAsync(p_sync, 0, 256 * sizeof(int));
    cudaMemsetAsync(p_ef, 0, (size_t)NFC * 128 * sizeof(float));
    cudaMemsetAsync(p_Dv, 0, (size_t)NFC * 128 * sizeof(float));
    cudaMemsetAsync(p_DA, 0, (size_t)NV  * 128 * sizeof(float));
    k_in<<<128, 128>>>(inputs, W_in, b_in, SB(1));

    for (int i = 0; i < LAYERS; i++) {
        const float* W0i  = W0  + (size_t)i * 256 * 128;
        const float* Wl1i = Wl1 + (size_t)i * 256 * 128;
        int c1 = 2 * i, c2 = 2 * i + 1;
        if ((i & 1) == 0) {
            // ---- DirResNet2: two fused spMM->stats->GEMM megakernels ----
            int* s1 = p_sync + (i / 2) * 8;
            int* s2 = s1 + 4;
            k_mega<false><<<GF, 256>>>(Di_rows, Di_cols, Di_vals, p_ev,
                                       p_Dv, NFC, s1,
                                       p_ef, p_Dv, NFC, W0i, b0 + i * 128,
                                       g0 + i * 256, be0 + i * 256, SB(c1), INV_F,
                                       nullptr, p_ef, SB(c1 + 4));
            k_mega<true><<<GN, 256>>>(DiA_rows, DiA_cols, DiA_vals, p_ef,
                                      p_DA, NV, s2,
                                      p_ev, p_DA, NV, Wl1i, bl1 + i * 128,
                                      g1 + i * 256, be1 + i * 256, SB(c2), INV_N,
                                      p_v, p_ev, SB(c2 + 1));
        } else {
            // ---- AvgResNet2 (avg columns folded; K halved) + Dv/DA re-zeroing ----
            k_gemm8<false><<<GN, 256>>>(p_ev, NV, W0i, b0 + i * 128,
                                        g0 + i * 256, be0 + i * 256, SB(c1), INV_N,
                                        nullptr, p_ex, SB(c1 + 1), p_Dv, NFC * 32);
            k_gemm8<true><<<GN, 256>>>(p_ex, NV, Wl1i, bl1 + i * 128,
                                       g1 + i * 256, be1 + i * 256, SB(c2), INV_N,
                                       p_v, p_ev, SB(c2 + 2), p_DA, NV * 32);
        }
    }

    // final head: elu( BN(v) @ W_out + b_out )
    k_stats128<<<296, 256>>>((const float4*)p_v, NV, SB(62), 0);
    k_head_prep<<<1, 128>>>(g2, be2, W_out, b_out, SB(62), INV_N);
    k_final<<<(NV * 32 + 255) / 256, 256>>>(W_out, out);
}

// round 16
// speedup vs baseline: 1.4396x; 1.4396x over previous
#include <cuda_runtime.h>
#include <math.h>

// Problem constants
#define NV    5000
#define NFC   10000
#define LAYERS 30
#define NNZT  480000
#define EPSBN 1e-5f

typedef unsigned long long u64t;

// ---------------- device scratch ----------------
__device__ __align__(16) float g_v [NV  * 128];
__device__ __align__(16) float g_ev[NV  * 128];
__device__ __align__(16) float g_ef[NFC * 128];
__device__ __align__(16) float g_ex[NV  * 128];
__device__ __align__(16) float g_Dv[NFC * 128];
__device__ __align__(16) float g_DA[NV  * 128];
__device__ float g_stats[64 * 512];
__device__ float g_a   [128];
__device__ float g_bout[1];

__device__ __forceinline__ float eluf(float x) {
    return x > 0.f ? x : (__expf(x) - 1.f);
}

// packed f32x2 FMA: two independent IEEE fp32 FMAs
__device__ __forceinline__ void ffma2(u64t& d, u64t a, u64t b) {
    asm("fma.rn.f32x2 %0, %1, %2, %0;" : "+l"(d) : "l"(a), "l"(b));
}
__device__ __forceinline__ u64t bcast2(float x) {
    u64t r; asm("mov.b64 %0, {%1, %1};" : "=l"(r) : "f"(x)); return r;
}

// ---------------- input projection ----------------
__global__ void k_in(const float* __restrict__ in, const float* __restrict__ Wi,
                     const float* __restrict__ bi, float* __restrict__ statp) {
    int c = threadIdx.x;  // 128
    float w0 = Wi[c], w1 = Wi[128 + c], w2 = Wi[256 + c], b = bi[c];
    float s = 0.f, s2 = 0.f;
    for (int n = blockIdx.x; n < NV; n += gridDim.x) {
        float val = b + in[n * 3] * w0 + in[n * 3 + 1] * w1 + in[n * 3 + 2] * w2;
        g_v [n * 128 + c] = val;
        float e = eluf(val);
        g_ev[n * 128 + c] = e;
        s += e; s2 += e * e;
    }
    atomicAdd(&statp[c], s);
    atomicAdd(&statp[256 + c], s2);
}

// ---------------- COO spMM: 8 threads/edge, float4 vector atomics ----------------
__global__ void k_spmm(const int* __restrict__ rows_, const int* __restrict__ cols_,
                       const float* __restrict__ vals,
                       const float* __restrict__ X, float* __restrict__ Y) {
    int idx = blockIdx.x * blockDim.x + threadIdx.x;
    int e = idx >> 3, d = idx & 7;
    if (e >= NNZT) return;
    int R = rows_[e], Cq = cols_[e];
    float v = vals[e];
    float4 xv = ((const float4*)X)[(Cq >> 2) * 32 + (Cq & 3) * 8 + d];
    float4* yp = (float4*)Y + (R >> 2) * 32 + (R & 3) * 8 + d;
    asm volatile("red.global.add.v4.f32 [%0], {%1,%2,%3,%4};"
                 :: "l"(yp), "f"(v * xv.x), "f"(v * xv.y), "f"(v * xv.z), "f"(v * xv.w)
                 : "memory");
}

// ---------------- column stats (float4, 8 row-groups x 32 threads) --------------
__global__ void __launch_bounds__(256)
k_stats128(const float4* __restrict__ X4, int rows,
           float* __restrict__ statp, int off) {
    __shared__ float r1[8][128];
    __shared__ float r2[8][128];
    int tid = threadIdx.x;
    int c4 = tid & 31;
    int g  = tid >> 5;
    float4 s  = make_float4(0.f, 0.f, 0.f, 0.f);
    float4 s2 = make_float4(0.f, 0.f, 0.f, 0.f);
    for (int r = blockIdx.x * 8 + g; r < rows; r += gridDim.x * 8) {
        float4 x = X4[r * 32 + c4];
        s.x += x.x; s.y += x.y; s.z += x.z; s.w += x.w;
        s2.x += x.x * x.x; s2.y += x.y * x.y;
        s2.z += x.z * x.z; s2.w += x.w * x.w;
    }
    r1[g][c4 * 4 + 0] = s.x;  r1[g][c4 * 4 + 1] = s.y;
    r1[g][c4 * 4 + 2] = s.z;  r1[g][c4 * 4 + 3] = s.w;
    r2[g][c4 * 4 + 0] = s2.x; r2[g][c4 * 4 + 1] = s2.y;
    r2[g][c4 * 4 + 2] = s2.z; r2[g][c4 * 4 + 3] = s2.w;
    __syncthreads();
    if (tid < 128) {
        float a = 0.f;
#pragma unroll
        for (int w = 0; w < 8; w++) a += r1[w][tid];
        atomicAdd(&statp[off + tid], a);
    } else {
        int c = tid - 128;
        float a = 0.f;
#pragma unroll
        for (int w = 0; w < 8; w++) a += r2[w][c];
        atomicAdd(&statp[256 + off + c], a);
    }
}

// ---------------- fused BN + bias-fold + GEMM + elu + stats ----------------
// MR = rows per CTA (64 for face, 32 for vertex -> 2x CTAs for latency hiding).
// 64-col split via blockIdx.y. FFMA2 inner loop. Balanced bias fold.
template<int KT, bool ACC, int MR>
__global__ void __launch_bounds__(256)
k_gemm(const float* __restrict__ L, const float* __restrict__ R, int rows,
       const float* __restrict__ W, const float* __restrict__ bvec,
       const float* __restrict__ gamma, const float* __restrict__ beta,
       const float* __restrict__ statp_in, float invn,
       float* __restrict__ Vout, float* __restrict__ Eout,
       float* __restrict__ statp_out,
       float* __restrict__ Zbuf, int nz4) {
    constexpr int RT = MR / 8;        // rows per thread (8 or 4)
    constexpr int NP = RT / 2;        // packed row-pairs (4 or 2)
    __shared__ __align__(16) float As[2][16][MR + 8];
    __shared__ __align__(16) float Bs[2][16][72];
    __shared__ float sSc[256];
    __shared__ float sT [256];
    __shared__ float sB [64];
    __shared__ float sBp[256];
    int tid = threadIdx.x;  // 256
    int col0 = blockIdx.y * 64;

    if (KT == 16 || tid < 128) {
        float mean = statp_in[tid] * invn;
        float var  = fmaxf(statp_in[256 + tid] * invn - mean * mean, 0.f);
        float a = gamma[tid] * rsqrtf(var + EPSBN);
        sSc[tid] = a;
        sT[tid]  = beta[tid] - mean * a;
    } else {
        sT[tid] = beta[tid];   // broadcast-avg columns: var==0 -> BN out == beta
    }
    __syncthreads();

    int row0 = blockIdx.x * MR;
    int wc = tid & 31, wr = tid >> 5;
    u64t acc2[NP][2];
#pragma unroll
    for (int p = 0; p < NP; p++) { acc2[p][0] = 0ull; acc2[p][1] = 0ull; }
    float biasAcc = 0.f;
    int bcol = tid & 63, bq = tid >> 6;

    int am = tid >> 2, ak4 = (tid & 3) * 4;   // A loader: MR rows x 16 k, float4 each
    int bk = tid >> 4, bc = (tid & 15) * 4;
    float4 rA, rB;
    bool aload = (MR == 64) || (tid < 128);   // guard matches am range (R7 lesson)

    auto loadRegs = [&](int t) {
        int k0 = t * 16;
        const float* Ab = (KT == 16 && k0 >= 128) ? R : L;
        if (aload) {
            int r = row0 + am;
            rA = make_float4(0.f, 0.f, 0.f, 0.f);
            if (r < rows) rA = *(const float4*)&Ab[r * 128 + (k0 & 127) + ak4];
        }
        rB = *(const float4*)&W[(k0 + bk) * 128 + col0 + bc];
    };
    auto storeSmem = [&](int t, int b) {
        int k0 = t * 16;
        if (aload) {
            As[b][ak4 + 0][am] = rA.x * sSc[k0 + ak4 + 0];
            As[b][ak4 + 1][am] = rA.y * sSc[k0 + ak4 + 1];
            As[b][ak4 + 2][am] = rA.z * sSc[k0 + ak4 + 2];
            As[b][ak4 + 3][am] = rA.w * sSc[k0 + ak4 + 3];
        }
        *(float4*)&Bs[b][bk][bc] = rB;
    };

    loadRegs(0);
    storeSmem(0, 0);
    __syncthreads();
#pragma unroll 1
    for (int t = 0; t < KT; t++) {
        int b = t & 1;
        if (t + 1 < KT) loadRegs(t + 1);
        {   // balanced bias fold: 4 FMAs per thread per tile
            int kq = bq * 4;
#pragma unroll
            for (int k = 0; k < 4; k++)
                biasAcc += sT[t * 16 + kq + k] * Bs[b][kq + k][bcol];
        }
#pragma unroll
        for (int k = 0; k < 16; k++) {
            const ulonglong2* ap = (const ulonglong2*)&As[b][k][wr * RT];
            float2 b2 = *(const float2*)&Bs[b][k][wc * 2];
            u64t bx = bcast2(b2.x), by = bcast2(b2.y);
#pragma unroll
            for (int p = 0; p < NP; p += 2) {
                ulonglong2 av = ap[p >> 1];
                ffma2(acc2[p][0], av.x, bx); ffma2(acc2[p][1], av.x, by);
                ffma2(acc2[p + 1][0], av.y, bx); ffma2(acc2[p + 1][1], av.y, by);
            }
        }
        if (t + 1 < KT) storeSmem(t + 1, b ^ 1);
        __syncthreads();
    }

    float acc[RT][2];
#pragma unroll
    for (int p = 0; p < NP; p++)
#pragma unroll
        for (int c = 0; c < 2; c++)
            asm("mov.b64 {%0, %1}, %2;"
                : "=f"(acc[2 * p][c]), "=f"(acc[2 * p + 1][c]) : "l"(acc2[p][c]));

    if (KT == 8) {   // bias contribution of folded-away W rows 128..255
        int r0 = 128 + bq * 32;
#pragma unroll 8
        for (int rr = 0; rr < 32; rr++)
            biasAcc += sT[r0 + rr] * W[(r0 + rr) * 128 + col0 + bcol];
    }
    sBp[bq * 64 + bcol] = biasAcc;
    __syncthreads();
    if (tid < 64)
        sB[tid] = sBp[tid] + sBp[64 + tid] + sBp[128 + tid] + sBp[192 + tid]
                + bvec[col0 + tid];
    __syncthreads();

    float s1v[2] = {0.f, 0.f};
    float s2v[2] = {0.f, 0.f};
#pragma unroll
    for (int i = 0; i < RT; i++) {
        int r = row0 + wr * RT + i;
        if (r >= rows) continue;
        int C = col0 + wc * 2;
        float v0 = acc[i][0] + sB[wc * 2];
        float v1 = acc[i][1] + sB[wc * 2 + 1];
        if (ACC) {
            float2 old = *(float2*)&Vout[r * 128 + C];
            v0 += old.x; v1 += old.y;
            *(float2*)&Vout[r * 128 + C] = make_float2(v0, v1);
        }
        float e0 = eluf(v0), e1 = eluf(v1);
        *(float2*)&Eout[r * 128 + C] = make_float2(e0, e1);
        s1v[0] += e0; s1v[1] += e1;
        s2v[0] += e0 * e0; s2v[1] += e1 * e1;
    }
    float* red1 = &As[0][0][0];   // 8 warps x 64 cols partials
    float* red2 = &As[1][0][0];
    red1[wr * 64 + wc * 2]     = s1v[0];
    red1[wr * 64 + wc * 2 + 1] = s1v[1];
    red2[wr * 64 + wc * 2]     = s2v[0];
    red2[wr * 64 + wc * 2 + 1] = s2v[1];
    __syncthreads();
    if (tid < 64) {
        float s = 0.f;
#pragma unroll
        for (int w = 0; w < 8; w++) s += red1[w * 64 + tid];
        atomicAdd(&statp_out[col0 + tid], s);
    } else if (tid < 128) {
        int c = tid - 64;
        float s = 0.f;
#pragma unroll
        for (int w = 0; w < 8; w++) s += red2[w * 64 + c];
        atomicAdd(&statp_out[256 + col0 + c], s);
    }

    // tail: zero Dv/DA for the next even layer (KT==8 only; no concurrent readers)
    if (KT == 8 && Zbuf != nullptr) {
        int gt = (blockIdx.y * gridDim.x + blockIdx.x) * 256 + tid;
        int gs = gridDim.x * gridDim.y * 256;
        float4 z = make_float4(0.f, 0.f, 0.f, 0.f);
        for (int i = gt; i < nz4; i += gs) ((float4*)Zbuf)[i] = z;
    }
}

// ---------------- final head ----------------
__global__ void k_head_prep(const float* __restrict__ gamma, const float* __restrict__ beta,
                            const float* __restrict__ Wout, const float* __restrict__ bout,
                            const float* __restrict__ statp, float invn) {
    __shared__ float sh[128];
    int c = threadIdx.x;  // 128
    float mean = statp[c] * invn;
    float var  = fmaxf(statp[256 + c] * invn - mean * mean, 0.f);
    float a = gamma[c] * rsqrtf(var + EPSBN);
    g_a[c] = a;
    sh[c] = (beta[c] - mean * a) * Wout[c];
    __syncthreads();
    for (int s = 64; s > 0; s >>= 1) {
        if (c < s) sh[c] += sh[c + s];
        __syncthreads();
    }
    if (c == 0) g_bout[0] = bout[0] + sh[0];
}

__global__ void k_final(const float* __restrict__ Wout, float* __restrict__ out) {
    int warp = (blockIdx.x * blockDim.x + threadIdx.x) >> 5;
    int lane = threadIdx.x & 31;
    if (warp >= NV) return;
    float s = 0.f;
#pragma unroll
    for (int q = 0; q < 4; q++) {
        int c = q * 32 + lane;
        s += g_v[warp * 128 + c] * g_a[c] * Wout[c];
    }
#pragma unroll
    for (int o = 16; o; o >>= 1) s += __shfl_xor_sync(0xffffffffu, s, o);
    if (lane == 0) out[warp] = eluf(s + g_bout[0]);
}

// ---------------- host orchestration ----------------
extern "C" void kernel_launch(void* const* d_in, const int* in_sizes, int n_in,
                              void* d_out, int out_size) {
    const float* inputs   = (const float*)d_in[0];
    const int*   Di_rows  = (const int*)d_in[2];
    const int*   Di_cols  = (const int*)d_in[3];
    const float* Di_vals  = (const float*)d_in[4];
    const int*   DiA_rows = (const int*)d_in[5];
    const int*   DiA_cols = (const int*)d_in[6];
    const float* DiA_vals = (const float*)d_in[7];
    const float* W_in  = (const float*)d_in[8];
    const float* b_in  = (const float*)d_in[9];
    const float* g0    = (const float*)d_in[10];
    const float* be0   = (const float*)d_in[11];
    const float* W0    = (const float*)d_in[12];
    const float* b0    = (const float*)d_in[13];
    const float* g1    = (const float*)d_in[14];
    const float* be1   = (const float*)d_in[15];
    const float* Wl1   = (const float*)d_in[16];
    const float* bl1   = (const float*)d_in[17];
    const float* g2    = (const float*)d_in[18];
    const float* be2   = (const float*)d_in[19];
    const float* W_out = (const float*)d_in[20];
    const float* b_out = (const float*)d_in[21];
    float* out = (float*)d_out;
    (void)in_sizes; (void)n_in; (void)out_size;

    float *p_v, *p_ev, *p_ef, *p_ex, *p_Dv, *p_DA, *p_stats;
    cudaGetSymbolAddress((void**)&p_v,     g_v);
    cudaGetSymbolAddress((void**)&p_ev,    g_ev);
    cudaGetSymbolAddress((void**)&p_ef,    g_ef);
    cudaGetSymbolAddress((void**)&p_ex,    g_ex);
    cudaGetSymbolAddress((void**)&p_Dv,    g_Dv);
    cudaGetSymbolAddress((void**)&p_DA,    g_DA);
    cudaGetSymbolAddress((void**)&p_stats, g_stats);
    auto SB = [&](int i) { return p_stats + (size_t)i * 512; };

    const dim3 GF((NFC + 63) / 64, 2);   // face: 64-row tiles, 314 CTAs
    const dim3 GN((NV  + 31) / 32, 2);   // vertex: 32-row tiles, 314 CTAs
    const int GS = (NNZT * 8 + 255) / 256;
    const float INV_F = 1.0f / (float)NFC;
    const float INV_N = 1.0f / (float)NV;

    // replay-invariant init
    cudaMemsetAsync(p_stats, 0, (size_t)64 * 512 * sizeof(float));
    cudaMemsetAsync(p_ef, 0, (size_t)NFC * 128 * sizeof(float));
    cudaMemsetAsync(p_Dv, 0, (size_t)NFC * 128 * sizeof(float));
    cudaMemsetAsync(p_DA, 0, (size_t)NV  * 128 * sizeof(float));
    k_in<<<128, 128>>>(inputs, W_in, b_in, SB(1));

    for (int i = 0; i < LAYERS; i++) {
        const float* W0i  = W0  + (size_t)i * 256 * 128;
        const float* Wl1i = Wl1 + (size_t)i * 256 * 128;
        int c1 = 2 * i, c2 = 2 * i + 1;
        if ((i & 1) == 0) {
            // ---- DirResNet2 ----
            k_spmm<<<GS, 256>>>(Di_rows, Di_cols, Di_vals, p_ev, p_Dv);
            k_stats128<<<296, 256>>>((const float4*)p_Dv, NFC, SB(c1), 128);
            k_gemm<16, false, 64><<<GF, 256>>>(p_ef, p_Dv, NFC, W0i, b0 + i * 128,
                                               g0 + i * 256, be0 + i * 256, SB(c1), INV_F,
                                               nullptr, p_ef, SB(c1 + 4), nullptr, 0);
            k_spmm<<<GS, 256>>>(DiA_rows, DiA_cols, DiA_vals, p_ef, p_DA);
            k_stats128<<<296, 256>>>((const float4*)p_DA, NV, SB(c2), 128);
            k_gemm<16, true, 32><<<GN, 256>>>(p_ev, p_DA, NV, Wl1i, bl1 + i * 128,
                                              g1 + i * 256, be1 + i * 256, SB(c2), INV_N,
                                              p_v, p_ev, SB(c2 + 1), nullptr, 0);
        } else {
            // ---- AvgResNet2 (avg columns folded; K halved) + Dv/DA re-zeroing ----
            k_gemm<8, false, 32><<<GN, 256>>>(p_ev, nullptr, NV, W0i, b0 + i * 128,
                                              g0 + i * 256, be0 + i * 256, SB(c1), INV_N,
                                              nullptr, p_ex, SB(c1 + 1), p_Dv, NFC * 32);
            k_gemm<8, true, 32><<<GN, 256>>>(p_ex, nullptr, NV, Wl1i, bl1 + i * 128,
                                             g1 + i * 256, be1 + i * 256, SB(c2), INV_N,
                                             p_v, p_ev, SB(c2 + 2), p_DA, NV * 32);
        }
    }

    // final head: elu( BN(v) @ W_out + b_out )
    k_stats128<<<296, 256>>>((const float4*)p_v, NV, SB(62), 0);
    k_head_prep<<<1, 128>>>(g2, be2, W_out, b_out, SB(62), INV_N);
    k_final<<<(NV * 32 + 255) / 256, 256>>>(W_out, out);
}